// round 7
// baseline (speedup 1.0000x reference)
#include <cuda_runtime.h>
#include <cstdint>
#include <math.h>

// ---------------------------------------------------------------------------
// HierarchicalMoELayer: B=8 S=1024 DM=512 DF=2048, E=64, TOPK=2 (sm_100 base)
// route(1 kernel) -> roundx -> GEMM1(+GELU) -> GEMM2 -> combine
// GEMM: mma.sync m16n8k8 tf32. BM=256 BN=128 BK=32, 512 thr, 16 warps (4x4).
// A: 4-stage cp.async ring from pre-rounded tf32 buffers (deep MLP).
// B: LDG 2 tiles ahead -> cvt.rna -> STS, double-buffered smem.
// R6 fix: B chunk decomposition was BN=64-style (brow up to 63 -> OOB W read
// + smem overrun). Correct mapping: 1024 chunks, row=c>>5 (0..31), col=c&31.
// ---------------------------------------------------------------------------

#define kNSUB 8
#define kE    64
#define kT    8192
#define kA    16384
#define kDM   512
#define kDF   2048
#define kCAP  1024

#define BM 256
#define BN 128
#define BK 32
#define NTHR 512

#define AS_STR 36                 /* words/row: conflict-free frags, 16B-mult */
#define BS_STR 136
#define A_WORDS (BM * AS_STR)     /* 9216 words = 36 KB per stage */
#define B_WORDS (BK * BS_STR)     /* 4352 words = 17 KB per stage */
#define ASTG 4
#define SMEM_WORDS (ASTG * A_WORDS + 2 * B_WORDS)
#define SMEM_BYTES (SMEM_WORDS * 4)   /* 182272 B */

// --------------------------- device scratch ---------------------------------
__device__ int   g_cnt[kE];
__device__ int   g_off[kE];
__device__ int   g_slot[kA];
__device__ int   g_rowtok[kA];
__device__ float g_wa[kA];
__device__ float g_x [(size_t)kT * kDM];   // hidden pre-rounded to tf32
__device__ float g_h [(size_t)kA * kDF];   // GEMM1 out (GELU, rna-rounded)
__device__ float g_y2[(size_t)kA * kDM];   // GEMM2 out

// ------------------------------ helpers -------------------------------------
__device__ __forceinline__ uint32_t f2tf32(float x) {
    uint32_t r;
    asm("cvt.rna.tf32.f32 %0, %1;" : "=r"(r) : "f"(x));
    return r;
}
__device__ __forceinline__ void mma_tf32(float* d, const uint32_t* a, const uint32_t* b) {
    asm volatile(
        "mma.sync.aligned.m16n8k8.row.col.f32.tf32.tf32.f32 "
        "{%0,%1,%2,%3},{%4,%5,%6,%7},{%8,%9},{%0,%1,%2,%3};\n"
        : "+f"(d[0]), "+f"(d[1]), "+f"(d[2]), "+f"(d[3])
        : "r"(a[0]), "r"(a[1]), "r"(a[2]), "r"(a[3]),
          "r"(b[0]), "r"(b[1]));
}
__device__ __forceinline__ void cp_async16(uint32_t dst, const void* src) {
    asm volatile("cp.async.cg.shared.global [%0], [%1], 16;\n" :: "r"(dst), "l"(src));
}
__device__ __forceinline__ void cp_commit() { asm volatile("cp.async.commit_group;\n"); }
__device__ __forceinline__ void cp_wait2()  { asm volatile("cp.async.wait_group 2;\n"); }

// ------------------------------- routing (fused, 1 block) -------------------
__global__ void k_route(const int* __restrict__ cat, const int* __restrict__ sub,
                        const float* __restrict__ w) {
    __shared__ int scnt[kE], soff[kE], scur[kE];
    const int tid = threadIdx.x;   // 1024 threads
    if (tid < kE) scnt[tid] = 0;
    __syncthreads();
    int eloc[kA / 1024];
#pragma unroll
    for (int i = 0; i < kA / 1024; ++i) {
        int a = i * 1024 + tid;
        int e = cat[a] * kNSUB + sub[a];
        eloc[i] = e;
        atomicAdd(&scnt[e], 1);
    }
    __syncthreads();
    if (tid == 0) {
        int s = 0;
        for (int e = 0; e < kE; ++e) { soff[e] = s; s += scnt[e]; }
    }
    __syncthreads();
    if (tid < kE) {
        g_cnt[tid] = scnt[tid];
        g_off[tid] = soff[tid];
        scur[tid]  = 0;
    }
    __syncthreads();
#pragma unroll
    for (int i = 0; i < kA / 1024; ++i) {
        int a = i * 1024 + tid;
        int e = eloc[i];
        int pos  = atomicAdd(&scur[e], 1);
        int slot = soff[e] + pos;
        g_slot[a]      = slot;
        g_rowtok[slot] = a >> 1;
        g_wa[a]        = (pos < kCAP) ? w[a] : 0.f;
    }
}

// --------------------- pre-round hidden to tf32 (rna) ------------------------
__global__ void k_roundx(const float* __restrict__ h) {
    int i = blockIdx.x * 256 + threadIdx.x;     // over T*DM/4 float4s
    float4 v = reinterpret_cast<const float4*>(h)[i];
    uint4 u;
    u.x = f2tf32(v.x); u.y = f2tf32(v.y);
    u.z = f2tf32(v.z); u.w = f2tf32(v.w);
    reinterpret_cast<uint4*>(g_x)[i] = u;
}

// ------------------------------- grouped GEMM --------------------------------
// MODE 0: A = gathered g_x rows (pre-rounded), Out = g_h (bias+GELU, rna out)
// MODE 1: A = g_h compacted rows (pre-rounded), Out = g_y2 (bias only)
template<int KTOT, int NTOT, int MODE>
__global__ void __launch_bounds__(NTHR, 1)
k_gemm(const float* __restrict__ Wt, const float* __restrict__ bias)
{
    extern __shared__ uint32_t smem[];
    uint32_t* Abuf = smem;                     // [ASTG][BM][AS_STR]
    uint32_t* Bbuf = smem + ASTG * A_WORDS;    // [2][BK][BS_STR]

    const int e    = blockIdx.z;
    const int cnt  = g_cnt[e];
    const int row0 = blockIdx.y * BM;
    if (row0 >= cnt) return;

    const int off  = g_off[e];
    const int n0   = blockIdx.x * BN;
    const int tid  = threadIdx.x;
    const int lane = tid & 31;
    const int wid  = tid >> 5;
    const int wm   = wid & 3;       // 4 warp-rows of 64
    const int wn   = wid >> 2;      // 4 warp-cols of 32
    const int gq   = lane >> 2;     // 0..7
    const int tq   = lane & 3;      // 0..3

    // ---- A cp.async: 4 chunks/thread/stage. chunk c = i*512+tid ->
    //      row = tid>>3 + 64*i, 16B-chunk index ck = tid&7.
    const int arow0 = tid >> 3;
    const int ack   = tid & 7;
    const float* asrc[4];
#pragma unroll
    for (int i = 0; i < 4; ++i) {
        int r = arow0 + 64 * i;
        int lr = row0 + r;
        if (lr >= cnt) lr = cnt - 1;           // clamp: loads valid data, store guarded
        size_t base;
        if (MODE == 0) base = (size_t)g_rowtok[off + lr] * KTOT;
        else           base = (size_t)(off + lr) * KTOT;
        asrc[i] = (MODE == 0 ? g_x : g_h) + base + ack * 4;
    }
    const uint32_t aAddrBase = (uint32_t)__cvta_generic_to_shared(Abuf);

    auto cpA = [&](int kt) {
        uint32_t st = (uint32_t)(kt & (ASTG - 1));
#pragma unroll
        for (int i = 0; i < 4; ++i) {
            uint32_t dst = aAddrBase +
                (st * A_WORDS + (uint32_t)(arow0 + 64 * i) * AS_STR + ack * 4) * 4u;
            cp_async16(dst, asrc[i] + (size_t)kt * BK);
        }
        cp_commit();
    };

    // ---- B: 1024 16B chunks (32 rows x 32 chunks), 2 per thread.
    //      chunk c = j*512+tid -> row = c>>5 (0..31), col16 = c&31 (= tid&31).
    const int brow[2] = { tid >> 5, 16 + (tid >> 5) };
    const int bc16    = tid & 31;
    const float* wbase = Wt + (size_t)e * KTOT * NTOT + n0;

    float4 breg[2][2];
    auto ldgB = [&](int kt, int set) {
#pragma unroll
        for (int j = 0; j < 2; ++j)
            breg[set][j] = *reinterpret_cast<const float4*>(
                wbase + (size_t)(kt * BK + brow[j]) * NTOT + bc16 * 4);
    };
    auto stsB = [&](int kt, int set) {
        uint32_t* B0 = Bbuf + (kt & 1) * B_WORDS;
#pragma unroll
        for (int j = 0; j < 2; ++j) {
            uint4 u;
            u.x = f2tf32(breg[set][j].x); u.y = f2tf32(breg[set][j].y);
            u.z = f2tf32(breg[set][j].z); u.w = f2tf32(breg[set][j].w);
            *reinterpret_cast<uint4*>(&B0[brow[j] * BS_STR + bc16 * 4]) = u;
        }
    };

    float acc[4][4][4];
#pragma unroll
    for (int mi = 0; mi < 4; ++mi)
#pragma unroll
        for (int ni = 0; ni < 4; ++ni)
#pragma unroll
            for (int q = 0; q < 4; ++q) acc[mi][ni][q] = 0.f;

    constexpr int KT = KTOT / BK;

    // -------- prologue: A stages 0..2 in flight, B tile 0 in smem, 1 staged
    ldgB(0, 0);
    ldgB(1, 1);
    cpA(0); cpA(1); cpA(2);
    stsB(0, 0);
    cp_wait2();            // A(0) arrived (<=2 groups pending)
    __syncthreads();

    for (int kt = 0; kt < KT; ++kt) {
        if (kt + 2 < KT) ldgB(kt + 2, kt & 1);   // issue early, 2 tiles ahead

        const uint32_t* A0 = Abuf + (kt & (ASTG - 1)) * A_WORDS;
        const uint32_t* B0 = Bbuf + (kt & 1) * B_WORDS;

#pragma unroll
        for (int kk = 0; kk < BK; kk += 8) {
            uint32_t af[4][4], bf[4][2];
#pragma unroll
            for (int mi = 0; mi < 4; ++mi) {
                int r = wm * 64 + mi * 16 + gq;
                af[mi][0] = A0[r * AS_STR + kk + tq];
                af[mi][1] = A0[(r + 8) * AS_STR + kk + tq];
                af[mi][2] = A0[r * AS_STR + kk + tq + 4];
                af[mi][3] = A0[(r + 8) * AS_STR + kk + tq + 4];
            }
#pragma unroll
            for (int ni = 0; ni < 4; ++ni) {
                int c = wn * 32 + ni * 8 + gq;
                bf[ni][0] = B0[(kk + tq) * BS_STR + c];
                bf[ni][1] = B0[(kk + tq + 4) * BS_STR + c];
            }
#pragma unroll
            for (int mi = 0; mi < 4; ++mi)
#pragma unroll
                for (int ni = 0; ni < 4; ++ni)
                    mma_tf32(acc[mi][ni], af[mi], bf[ni]);
        }

        if (kt + 1 < KT) {
            stsB(kt + 1, (kt + 1) & 1);          // other smem buffer
            if (kt + 3 < KT) cpA(kt + 3);
            else             cp_commit();        // keep group count consistent
            cp_wait2();                          // A(kt+1) arrived
            __syncthreads();
        }
    }

    // ------------------------------ epilogue ---------------------------------
    float* Out = (MODE == 0) ? g_h : g_y2;
    const float* bp = bias + (size_t)e * NTOT;
#pragma unroll
    for (int mi = 0; mi < 4; ++mi) {
#pragma unroll
        for (int rr = 0; rr < 2; ++rr) {
            int lrow = row0 + wm * 64 + mi * 16 + gq + rr * 8;
            if (lrow < cnt) {
                float* op = Out + (size_t)(off + lrow) * NTOT;
#pragma unroll
                for (int ni = 0; ni < 4; ++ni) {
                    int c = n0 + wn * 32 + ni * 8 + tq * 2;
                    float v0 = acc[mi][ni][rr * 2 + 0] + bp[c];
                    float v1 = acc[mi][ni][rr * 2 + 1] + bp[c + 1];
                    if (MODE == 0) {   // exact GELU (erf), then rna-round for GEMM2's A
                        v0 = 0.5f * v0 * (1.f + erff(v0 * 0.70710678118654752f));
                        v1 = 0.5f * v1 * (1.f + erff(v1 * 0.70710678118654752f));
                        v0 = __uint_as_float(f2tf32(v0));
                        v1 = __uint_as_float(f2tf32(v1));
                    }
                    *reinterpret_cast<float2*>(op + c) = make_float2(v0, v1);
                }
            }
        }
    }
}

// ------------------------------- combine --------------------------------------
__global__ void k_combine(float* __restrict__ out) {
    int i = blockIdx.x * 256 + threadIdx.x;   // over T * (DM/4)
    if (i >= kT * (kDM / 4)) return;
    int t  = i >> 7;
    int d4 = i & 127;
    int a0 = t * 2, a1 = t * 2 + 1;
    float w0 = g_wa[a0], w1 = g_wa[a1];
    const float4 v0 = reinterpret_cast<const float4*>(g_y2 + (size_t)g_slot[a0] * kDM)[d4];
    const float4 v1 = reinterpret_cast<const float4*>(g_y2 + (size_t)g_slot[a1] * kDM)[d4];
    float4 r;
    r.x = w0 * v0.x + w1 * v1.x;
    r.y = w0 * v0.y + w1 * v1.y;
    r.z = w0 * v0.z + w1 * v1.z;
    r.w = w0 * v0.w + w1 * v1.w;
    reinterpret_cast<float4*>(out)[i] = r;
}

// ------------------------------- launch ----------------------------------------
extern "C" void kernel_launch(void* const* d_in, const int* in_sizes, int n_in,
                              void* d_out, int out_size) {
    const float* hidden = (const float*)d_in[0];
    const int*   cat    = (const int*)  d_in[1];
    const int*   sub    = (const int*)  d_in[2];
    const float* wts    = (const float*)d_in[3];
    const float* W1     = (const float*)d_in[4];
    const float* b1     = (const float*)d_in[5];
    const float* W2     = (const float*)d_in[6];
    const float* b2     = (const float*)d_in[7];
    float*       out    = (float*)d_out;

    (void)in_sizes; (void)n_in; (void)out_size;

    cudaFuncSetAttribute(k_gemm<kDM, kDF, 0>,
                         cudaFuncAttributeMaxDynamicSharedMemorySize, SMEM_BYTES);
    cudaFuncSetAttribute(k_gemm<kDF, kDM, 1>,
                         cudaFuncAttributeMaxDynamicSharedMemorySize, SMEM_BYTES);

    // Launch #1: fused routing (single block)
    k_route<<<1, 1024>>>(cat, sub, wts);
    // Launch #2: pre-round hidden for cp.async A path
    k_roundx<<<(kT * kDM / 4) / 256, 256>>>(hidden);

    // Launch #3: GEMM1 rows x 512 @ 512 x 2048 (+GELU) -> g_h
    dim3 g1(kDF / BN, (kCAP + BM - 1) / BM, kE);   // (16, 4, 64); y>=cnt exits
    k_gemm<kDM, kDF, 0><<<g1, NTHR, SMEM_BYTES>>>(W1, b1);

    // Launch #4 (ncu-captured): GEMM2 rows x 2048 @ 2048 x 512 -> g_y2
    dim3 g2(kDM / BN, (kCAP + BM - 1) / BM, kE);   // (4, 4, 64)
    k_gemm<kDF, kDM, 1><<<g2, NTHR, SMEM_BYTES>>>(W2, b2);

    // Launch #5: combine
    int ncomb = kT * (kDM / 4);
    k_combine<<<(ncomb + 255) / 256, 256>>>(out);
}

// round 8
// speedup vs baseline: 1.3848x; 1.3848x over previous
#include <cuda_runtime.h>
#include <cstdint>
#include <math.h>

// ---------------------------------------------------------------------------
// HierarchicalMoELayer: B=8 S=1024 DM=512 DF=2048, E=64, TOPK=2 (sm_100 base)
// route -> roundx -> GEMM1(+GELU) -> GEMM2 -> combine
// GEMM: mma.sync m16n8k8 tf32. CTA 128x128xBK32, 256 thr, 8 warps (2x4),
// warp tile 64x32. A: 3-stage cp.async ring (pre-rounded tf32 sources).
// B: LDG 1 tile ahead -> cvt.rna -> STS, double buffer. 88KB smem => 2 CTA/SM
// (two barrier domains overlap; R7 profile showed occ=25%/1 CTA/SM with
// tensor=46.5% — barrier-serialized).
// ---------------------------------------------------------------------------

#define kNSUB 8
#define kE    64
#define kT    8192
#define kA    16384
#define kDM   512
#define kDF   2048
#define kCAP  1024

#define BM 128
#define BN 128
#define BK 32
#define NTHR 256

#define AS_STR 36                 /* words/row: conflict-free frags, 16B-mult */
#define BS_STR 136
#define A_WORDS (BM * AS_STR)     /* 4608 words = 18 KB per stage */
#define B_WORDS (BK * BS_STR)     /* 4352 words = 17 KB per stage */
#define ASTG 3
#define SMEM_WORDS (ASTG * A_WORDS + 2 * B_WORDS)
#define SMEM_BYTES (SMEM_WORDS * 4)   /* 90112 B -> 2 CTAs/SM */

// --------------------------- device scratch ---------------------------------
__device__ int   g_cnt[kE];
__device__ int   g_off[kE];
__device__ int   g_slot[kA];
__device__ int   g_rowtok[kA];
__device__ float g_wa[kA];
__device__ float g_x [(size_t)kT * kDM];   // hidden pre-rounded to tf32
__device__ float g_h [(size_t)kA * kDF];   // GEMM1 out (GELU, rna-rounded)
__device__ float g_y2[(size_t)kA * kDM];   // GEMM2 out

// ------------------------------ helpers -------------------------------------
__device__ __forceinline__ uint32_t f2tf32(float x) {
    uint32_t r;
    asm("cvt.rna.tf32.f32 %0, %1;" : "=r"(r) : "f"(x));
    return r;
}
__device__ __forceinline__ void mma_tf32(float* d, const uint32_t* a, const uint32_t* b) {
    asm volatile(
        "mma.sync.aligned.m16n8k8.row.col.f32.tf32.tf32.f32 "
        "{%0,%1,%2,%3},{%4,%5,%6,%7},{%8,%9},{%0,%1,%2,%3};\n"
        : "+f"(d[0]), "+f"(d[1]), "+f"(d[2]), "+f"(d[3])
        : "r"(a[0]), "r"(a[1]), "r"(a[2]), "r"(a[3]),
          "r"(b[0]), "r"(b[1]));
}
__device__ __forceinline__ void cp_async16(uint32_t dst, const void* src) {
    asm volatile("cp.async.cg.shared.global [%0], [%1], 16;\n" :: "r"(dst), "l"(src));
}
__device__ __forceinline__ void cp_commit() { asm volatile("cp.async.commit_group;\n"); }
__device__ __forceinline__ void cp_wait1()  { asm volatile("cp.async.wait_group 1;\n"); }

// ------------------------------- routing (fused, 1 block) -------------------
__global__ void k_route(const int* __restrict__ cat, const int* __restrict__ sub,
                        const float* __restrict__ w) {
    __shared__ int scnt[kE], soff[kE], scur[kE];
    const int tid = threadIdx.x;   // 1024 threads
    if (tid < kE) scnt[tid] = 0;
    __syncthreads();
    int eloc[kA / 1024];
#pragma unroll
    for (int i = 0; i < kA / 1024; ++i) {
        int a = i * 1024 + tid;
        int e = cat[a] * kNSUB + sub[a];
        eloc[i] = e;
        atomicAdd(&scnt[e], 1);
    }
    __syncthreads();
    if (tid == 0) {
        int s = 0;
        for (int e = 0; e < kE; ++e) { soff[e] = s; s += scnt[e]; }
    }
    __syncthreads();
    if (tid < kE) {
        g_cnt[tid] = scnt[tid];
        g_off[tid] = soff[tid];
        scur[tid]  = 0;
    }
    __syncthreads();
#pragma unroll
    for (int i = 0; i < kA / 1024; ++i) {
        int a = i * 1024 + tid;
        int e = eloc[i];
        int pos  = atomicAdd(&scur[e], 1);
        int slot = soff[e] + pos;
        g_slot[a]      = slot;
        g_rowtok[slot] = a >> 1;
        g_wa[a]        = (pos < kCAP) ? w[a] : 0.f;
    }
}

// --------------------- pre-round hidden to tf32 (rna) ------------------------
__global__ void k_roundx(const float* __restrict__ h) {
    int i = blockIdx.x * 256 + threadIdx.x;     // over T*DM/4 float4s
    float4 v = reinterpret_cast<const float4*>(h)[i];
    uint4 u;
    u.x = f2tf32(v.x); u.y = f2tf32(v.y);
    u.z = f2tf32(v.z); u.w = f2tf32(v.w);
    reinterpret_cast<uint4*>(g_x)[i] = u;
}

// ------------------------------- grouped GEMM --------------------------------
// MODE 0: A = gathered g_x rows (pre-rounded), Out = g_h (bias+GELU, rna out)
// MODE 1: A = g_h compacted rows (pre-rounded), Out = g_y2 (bias only)
template<int KTOT, int NTOT, int MODE>
__global__ void __launch_bounds__(NTHR, 2)
k_gemm(const float* __restrict__ Wt, const float* __restrict__ bias)
{
    extern __shared__ uint32_t smem[];
    uint32_t* Abuf = smem;                     // [ASTG][BM][AS_STR]
    uint32_t* Bbuf = smem + ASTG * A_WORDS;    // [2][BK][BS_STR]

    const int e    = blockIdx.z;
    const int cnt  = g_cnt[e];
    const int row0 = blockIdx.y * BM;
    if (row0 >= cnt) return;

    const int off  = g_off[e];
    const int n0   = blockIdx.x * BN;
    const int tid  = threadIdx.x;
    const int lane = tid & 31;
    const int wid  = tid >> 5;
    const int wm   = wid & 1;       // 2 warp-rows of 64
    const int wn   = wid >> 1;      // 4 warp-cols of 32
    const int gq   = lane >> 2;     // 0..7
    const int tq   = lane & 3;      // 0..3

    // ---- A cp.async: 1024 16B chunks/stage, 4 per thread.
    //      chunk c = i*256+tid -> row = i*32 + (tid>>3), ck = tid&7.
    const int arow0 = tid >> 3;     // 0..31
    const int ack   = tid & 7;
    const float* asrc[4];
#pragma unroll
    for (int i = 0; i < 4; ++i) {
        int lr = row0 + arow0 + 32 * i;
        if (lr >= cnt) lr = cnt - 1;           // clamp: valid data, store guarded
        size_t base;
        if (MODE == 0) base = (size_t)g_rowtok[off + lr] * KTOT;
        else           base = (size_t)(off + lr) * KTOT;
        asrc[i] = (MODE == 0 ? g_x : g_h) + base + ack * 4;
    }
    const uint32_t aAddrBase = (uint32_t)__cvta_generic_to_shared(Abuf);

    auto cpA = [&](int kt) {
        uint32_t st = (uint32_t)(kt % ASTG);
#pragma unroll
        for (int i = 0; i < 4; ++i) {
            uint32_t dst = aAddrBase +
                (st * A_WORDS + (uint32_t)(arow0 + 32 * i) * AS_STR + ack * 4) * 4u;
            cp_async16(dst, asrc[i] + (size_t)kt * BK);
        }
        cp_commit();
    };

    // ---- B: 1024 16B chunks (32 rows x 32 chunks), 4 per thread.
    //      chunk c = j*256+tid -> row = j*8 + (tid>>5), col16 = tid&31.
    const int brow0 = tid >> 5;     // 0..7
    const int bc16  = tid & 31;
    const float* wbase = Wt + (size_t)e * KTOT * NTOT + n0;

    float4 breg[4];
    auto ldgB = [&](int kt) {
#pragma unroll
        for (int j = 0; j < 4; ++j)
            breg[j] = *reinterpret_cast<const float4*>(
                wbase + (size_t)(kt * BK + j * 8 + brow0) * NTOT + bc16 * 4);
    };
    auto stsB = [&](int kt) {
        uint32_t* B0 = Bbuf + (kt & 1) * B_WORDS;
#pragma unroll
        for (int j = 0; j < 4; ++j) {
            uint4 u;
            u.x = f2tf32(breg[j].x); u.y = f2tf32(breg[j].y);
            u.z = f2tf32(breg[j].z); u.w = f2tf32(breg[j].w);
            *reinterpret_cast<uint4*>(&B0[(j * 8 + brow0) * BS_STR + bc16 * 4]) = u;
        }
    };

    float acc[4][4][4];
#pragma unroll
    for (int mi = 0; mi < 4; ++mi)
#pragma unroll
        for (int ni = 0; ni < 4; ++ni)
#pragma unroll
            for (int q = 0; q < 4; ++q) acc[mi][ni][q] = 0.f;

    constexpr int KT = KTOT / BK;

    // -------- prologue: A stages 0,1 in flight; B tile 0 in smem
    ldgB(0);
    cpA(0); cpA(1);
    stsB(0);
    cp_wait1();            // A(0) arrived (<=1 group pending)
    __syncthreads();

    for (int kt = 0; kt < KT; ++kt) {
        if (kt + 1 < KT) ldgB(kt + 1);           // LDG early; hidden by mma

        const uint32_t* A0 = Abuf + (kt % ASTG) * A_WORDS;
        const uint32_t* B0 = Bbuf + (kt & 1) * B_WORDS;

#pragma unroll
        for (int kk = 0; kk < BK; kk += 8) {
            uint32_t af[4][4], bf[4][2];
#pragma unroll
            for (int mi = 0; mi < 4; ++mi) {
                int r = wm * 64 + mi * 16 + gq;
                af[mi][0] = A0[r * AS_STR + kk + tq];
                af[mi][1] = A0[(r + 8) * AS_STR + kk + tq];
                af[mi][2] = A0[r * AS_STR + kk + tq + 4];
                af[mi][3] = A0[(r + 8) * AS_STR + kk + tq + 4];
            }
#pragma unroll
            for (int ni = 0; ni < 4; ++ni) {
                int c = wn * 32 + ni * 8 + gq;
                bf[ni][0] = B0[(kk + tq) * BS_STR + c];
                bf[ni][1] = B0[(kk + tq + 4) * BS_STR + c];
            }
#pragma unroll
            for (int mi = 0; mi < 4; ++mi)
#pragma unroll
                for (int ni = 0; ni < 4; ++ni)
                    mma_tf32(acc[mi][ni], af[mi], bf[ni]);
        }

        if (kt + 1 < KT) {
            stsB(kt + 1);                        // other smem buffer (barrier-safe)
            if (kt + 2 < KT) cpA(kt + 2);
            else             cp_commit();        // keep group count consistent
            cp_wait1();                          // A(kt+1) arrived
            __syncthreads();                     // one sync per k-tile
        }
    }

    // ------------------------------ epilogue ---------------------------------
    float* Out = (MODE == 0) ? g_h : g_y2;
    const float* bp = bias + (size_t)e * NTOT;
#pragma unroll
    for (int mi = 0; mi < 4; ++mi) {
#pragma unroll
        for (int rr = 0; rr < 2; ++rr) {
            int lrow = row0 + wm * 64 + mi * 16 + gq + rr * 8;
            if (lrow < cnt) {
                float* op = Out + (size_t)(off + lrow) * NTOT;
#pragma unroll
                for (int ni = 0; ni < 4; ++ni) {
                    int c = n0 + wn * 32 + ni * 8 + tq * 2;
                    float v0 = acc[mi][ni][rr * 2 + 0] + bp[c];
                    float v1 = acc[mi][ni][rr * 2 + 1] + bp[c + 1];
                    if (MODE == 0) {   // exact GELU (erf), then rna-round for GEMM2's A
                        v0 = 0.5f * v0 * (1.f + erff(v0 * 0.70710678118654752f));
                        v1 = 0.5f * v1 * (1.f + erff(v1 * 0.70710678118654752f));
                        v0 = __uint_as_float(f2tf32(v0));
                        v1 = __uint_as_float(f2tf32(v1));
                    }
                    *reinterpret_cast<float2*>(op + c) = make_float2(v0, v1);
                }
            }
        }
    }
}

// ------------------------------- combine --------------------------------------
__global__ void k_combine(float* __restrict__ out) {
    int i = blockIdx.x * 256 + threadIdx.x;   // over T * (DM/4)
    if (i >= kT * (kDM / 4)) return;
    int t  = i >> 7;
    int d4 = i & 127;
    int a0 = t * 2, a1 = t * 2 + 1;
    float w0 = g_wa[a0], w1 = g_wa[a1];
    const float4 v0 = reinterpret_cast<const float4*>(g_y2 + (size_t)g_slot[a0] * kDM)[d4];
    const float4 v1 = reinterpret_cast<const float4*>(g_y2 + (size_t)g_slot[a1] * kDM)[d4];
    float4 r;
    r.x = w0 * v0.x + w1 * v1.x;
    r.y = w0 * v0.y + w1 * v1.y;
    r.z = w0 * v0.z + w1 * v1.z;
    r.w = w0 * v0.w + w1 * v1.w;
    reinterpret_cast<float4*>(out)[i] = r;
}

// ------------------------------- launch ----------------------------------------
extern "C" void kernel_launch(void* const* d_in, const int* in_sizes, int n_in,
                              void* d_out, int out_size) {
    const float* hidden = (const float*)d_in[0];
    const int*   cat    = (const int*)  d_in[1];
    const int*   sub    = (const int*)  d_in[2];
    const float* wts    = (const float*)d_in[3];
    const float* W1     = (const float*)d_in[4];
    const float* b1     = (const float*)d_in[5];
    const float* W2     = (const float*)d_in[6];
    const float* b2     = (const float*)d_in[7];
    float*       out    = (float*)d_out;

    (void)in_sizes; (void)n_in; (void)out_size;

    cudaFuncSetAttribute(k_gemm<kDM, kDF, 0>,
                         cudaFuncAttributeMaxDynamicSharedMemorySize, SMEM_BYTES);
    cudaFuncSetAttribute(k_gemm<kDF, kDM, 1>,
                         cudaFuncAttributeMaxDynamicSharedMemorySize, SMEM_BYTES);

    // Launch #1: fused routing (single block)
    k_route<<<1, 1024>>>(cat, sub, wts);
    // Launch #2: pre-round hidden for cp.async A path
    k_roundx<<<(kT * kDM / 4) / 256, 256>>>(hidden);

    // Launch #3: GEMM1 rows x 512 @ 512 x 2048 (+GELU) -> g_h
    dim3 g1(kDF / BN, (kCAP + BM - 1) / BM, kE);   // (16, 8, 64)
    k_gemm<kDM, kDF, 0><<<g1, NTHR, SMEM_BYTES>>>(W1, b1);

    // Launch #4 (ncu-captured): GEMM2 rows x 2048 @ 2048 x 512 -> g_y2
    dim3 g2(kDM / BN, (kCAP + BM - 1) / BM, kE);   // (4, 8, 64)
    k_gemm<kDF, kDM, 1><<<g2, NTHR, SMEM_BYTES>>>(W2, b2);

    // Launch #5: combine
    int ncomb = kT * (kDM / 4);
    k_combine<<<(ncomb + 255) / 256, 256>>>(out);
}

// round 9
// speedup vs baseline: 1.3860x; 1.0009x over previous
#include <cuda_runtime.h>
#include <cstdint>
#include <math.h>

// ---------------------------------------------------------------------------
// HierarchicalMoELayer: B=8 S=1024 DM=512 DF=2048, E=64, TOPK=2 (sm_100 base)
// route -> roundx -> GEMM1(+GELU) -> GEMM2 -> combine
// GEMM: mma.sync m16n8k8 tf32. CTA 128x128xBK32, 256 thr, 8 warps (2x4),
// warp tile 64x32, 2 CTAs/SM (register-capped at 128 regs).
// R9: ASTG=4 A-ring + period-4 unrolled mainloop -> static stage indices
// (kills ALU indexing, deepens A prefetch to 3 stages ahead).
// ---------------------------------------------------------------------------

#define kNSUB 8
#define kE    64
#define kT    8192
#define kA    16384
#define kDM   512
#define kDF   2048
#define kCAP  1024

#define BM 128
#define BN 128
#define BK 32
#define NTHR 256

#define AS_STR 36                 /* words/row: conflict-free frags, 16B-mult */
#define BS_STR 136
#define A_WORDS (BM * AS_STR)     /* 4608 words = 18 KB per stage */
#define B_WORDS (BK * BS_STR)     /* 4352 words = 17 KB per stage */
#define ASTG 4
#define SMEM_WORDS (ASTG * A_WORDS + 2 * B_WORDS)
#define SMEM_BYTES (SMEM_WORDS * 4)   /* 108544 B -> 2 CTAs/SM */

// --------------------------- device scratch ---------------------------------
__device__ int   g_cnt[kE];
__device__ int   g_off[kE];
__device__ int   g_slot[kA];
__device__ int   g_rowtok[kA];
__device__ float g_wa[kA];
__device__ float g_x [(size_t)kT * kDM];   // hidden pre-rounded to tf32
__device__ float g_h [(size_t)kA * kDF];   // GEMM1 out (GELU, rna-rounded)
__device__ float g_y2[(size_t)kA * kDM];   // GEMM2 out

// ------------------------------ helpers -------------------------------------
__device__ __forceinline__ uint32_t f2tf32(float x) {
    uint32_t r;
    asm("cvt.rna.tf32.f32 %0, %1;" : "=r"(r) : "f"(x));
    return r;
}
__device__ __forceinline__ void mma_tf32(float* d, const uint32_t* a, const uint32_t* b) {
    asm volatile(
        "mma.sync.aligned.m16n8k8.row.col.f32.tf32.tf32.f32 "
        "{%0,%1,%2,%3},{%4,%5,%6,%7},{%8,%9},{%0,%1,%2,%3};\n"
        : "+f"(d[0]), "+f"(d[1]), "+f"(d[2]), "+f"(d[3])
        : "r"(a[0]), "r"(a[1]), "r"(a[2]), "r"(a[3]),
          "r"(b[0]), "r"(b[1]));
}
__device__ __forceinline__ void cp_async16(uint32_t dst, const void* src) {
    asm volatile("cp.async.cg.shared.global [%0], [%1], 16;\n" :: "r"(dst), "l"(src));
}
__device__ __forceinline__ void cp_commit() { asm volatile("cp.async.commit_group;\n"); }
__device__ __forceinline__ void cp_wait2()  { asm volatile("cp.async.wait_group 2;\n"); }

// ------------------------------- routing (fused, 1 block) -------------------
__global__ void k_route(const int* __restrict__ cat, const int* __restrict__ sub,
                        const float* __restrict__ w) {
    __shared__ int scnt[kE], soff[kE], scur[kE];
    const int tid = threadIdx.x;   // 1024 threads
    if (tid < kE) scnt[tid] = 0;
    __syncthreads();
    int eloc[kA / 1024];
#pragma unroll
    for (int i = 0; i < kA / 1024; ++i) {
        int a = i * 1024 + tid;
        int e = cat[a] * kNSUB + sub[a];
        eloc[i] = e;
        atomicAdd(&scnt[e], 1);
    }
    __syncthreads();
    if (tid == 0) {
        int s = 0;
        for (int e = 0; e < kE; ++e) { soff[e] = s; s += scnt[e]; }
    }
    __syncthreads();
    if (tid < kE) {
        g_cnt[tid] = scnt[tid];
        g_off[tid] = soff[tid];
        scur[tid]  = 0;
    }
    __syncthreads();
#pragma unroll
    for (int i = 0; i < kA / 1024; ++i) {
        int a = i * 1024 + tid;
        int e = eloc[i];
        int pos  = atomicAdd(&scur[e], 1);
        int slot = soff[e] + pos;
        g_slot[a]      = slot;
        g_rowtok[slot] = a >> 1;
        g_wa[a]        = (pos < kCAP) ? w[a] : 0.f;
    }
}

// --------------------- pre-round hidden to tf32 (rna) ------------------------
__global__ void k_roundx(const float* __restrict__ h) {
    int i = blockIdx.x * 256 + threadIdx.x;     // over T*DM/4 float4s
    float4 v = reinterpret_cast<const float4*>(h)[i];
    uint4 u;
    u.x = f2tf32(v.x); u.y = f2tf32(v.y);
    u.z = f2tf32(v.z); u.w = f2tf32(v.w);
    reinterpret_cast<uint4*>(g_x)[i] = u;
}

// ------------------------------- grouped GEMM --------------------------------
// MODE 0: A = gathered g_x rows (pre-rounded), Out = g_h (bias+GELU, rna out)
// MODE 1: A = g_h compacted rows (pre-rounded), Out = g_y2 (bias only)
template<int KTOT, int NTOT, int MODE>
__global__ void __launch_bounds__(NTHR, 2)
k_gemm(const float* __restrict__ Wt, const float* __restrict__ bias)
{
    extern __shared__ uint32_t smem[];
    uint32_t* Abuf = smem;                     // [ASTG][BM][AS_STR]
    uint32_t* Bbuf = smem + ASTG * A_WORDS;    // [2][BK][BS_STR]

    const int e    = blockIdx.z;
    const int cnt  = g_cnt[e];
    const int row0 = blockIdx.y * BM;
    if (row0 >= cnt) return;

    const int off  = g_off[e];
    const int n0   = blockIdx.x * BN;
    const int tid  = threadIdx.x;
    const int lane = tid & 31;
    const int wid  = tid >> 5;
    const int wm   = wid & 1;       // 2 warp-rows of 64
    const int wn   = wid >> 1;      // 4 warp-cols of 32
    const int gq   = lane >> 2;     // 0..7
    const int tq   = lane & 3;      // 0..3

    // ---- A cp.async: 1024 16B chunks/stage, 4 per thread.
    const int arow0 = tid >> 3;     // 0..31
    const int ack   = tid & 7;
    const float* asrc[4];
#pragma unroll
    for (int i = 0; i < 4; ++i) {
        int lr = row0 + arow0 + 32 * i;
        if (lr >= cnt) lr = cnt - 1;           // clamp: valid data, store guarded
        size_t base;
        if (MODE == 0) base = (size_t)g_rowtok[off + lr] * KTOT;
        else           base = (size_t)(off + lr) * KTOT;
        asrc[i] = (MODE == 0 ? g_x : g_h) + base + ack * 4;
    }
    const uint32_t aAddrBase = (uint32_t)__cvta_generic_to_shared(Abuf);

    // st is a COMPILE-TIME stage index in all call sites (unrolled loop)
    auto cpA = [&](int kt, int st) {
#pragma unroll
        for (int i = 0; i < 4; ++i) {
            uint32_t dst = aAddrBase +
                (uint32_t)(st * A_WORDS + (arow0 + 32 * i) * AS_STR + ack * 4) * 4u;
            cp_async16(dst, asrc[i] + (size_t)kt * BK);
        }
        cp_commit();
    };

    // ---- B: 1024 16B chunks (32 rows x 32 chunks), 4 per thread.
    const int brow0 = tid >> 5;     // 0..7
    const int bc16  = tid & 31;
    const float* wbase = Wt + (size_t)e * KTOT * NTOT + n0;

    float4 breg[4];
    auto ldgB = [&](int kt) {
#pragma unroll
        for (int j = 0; j < 4; ++j)
            breg[j] = *reinterpret_cast<const float4*>(
                wbase + (size_t)(kt * BK + j * 8 + brow0) * NTOT + bc16 * 4);
    };
    auto stsB = [&](int st) {       // st compile-time
        uint32_t* B0 = Bbuf + st * B_WORDS;
#pragma unroll
        for (int j = 0; j < 4; ++j) {
            uint4 u;
            u.x = f2tf32(breg[j].x); u.y = f2tf32(breg[j].y);
            u.z = f2tf32(breg[j].z); u.w = f2tf32(breg[j].w);
            *reinterpret_cast<uint4*>(&B0[(j * 8 + brow0) * BS_STR + bc16 * 4]) = u;
        }
    };

    float acc[4][4][4];
#pragma unroll
    for (int mi = 0; mi < 4; ++mi)
#pragma unroll
        for (int ni = 0; ni < 4; ++ni)
#pragma unroll
            for (int q = 0; q < 4; ++q) acc[mi][ni][q] = 0.f;

    // mma block over one k-tile; stage indices compile-time via template-like lambda
    auto mma_tile = [&](int ast, int bst) {
        const uint32_t* A0 = Abuf + ast * A_WORDS;
        const uint32_t* B0 = Bbuf + bst * B_WORDS;
#pragma unroll
        for (int kk = 0; kk < BK; kk += 8) {
            uint32_t af[4][4], bf[4][2];
#pragma unroll
            for (int mi = 0; mi < 4; ++mi) {
                int r = wm * 64 + mi * 16 + gq;
                af[mi][0] = A0[r * AS_STR + kk + tq];
                af[mi][1] = A0[(r + 8) * AS_STR + kk + tq];
                af[mi][2] = A0[r * AS_STR + kk + tq + 4];
                af[mi][3] = A0[(r + 8) * AS_STR + kk + tq + 4];
            }
#pragma unroll
            for (int ni = 0; ni < 4; ++ni) {
                int c = wn * 32 + ni * 8 + gq;
                bf[ni][0] = B0[(kk + tq) * BS_STR + c];
                bf[ni][1] = B0[(kk + tq + 4) * BS_STR + c];
            }
#pragma unroll
            for (int mi = 0; mi < 4; ++mi)
#pragma unroll
                for (int ni = 0; ni < 4; ++ni)
                    mma_tf32(acc[mi][ni], af[mi], bf[ni]);
        }
    };

    constexpr int KT = KTOT / BK;          // 16 or 64; divisible by 4
    static_assert(KT % 4 == 0, "KT must be divisible by 4");

    // -------- prologue: A stages 0..2 in flight; B tile 0 in smem
    ldgB(0);
    cpA(0, 0); cpA(1, 1); cpA(2, 2);
    stsB(0);
    cp_wait2();            // A(0) arrived (2 groups pending)
    __syncthreads();

    for (int ktb = 0; ktb < KT; ktb += 4) {
#pragma unroll
        for (int u = 0; u < 4; ++u) {
            const int kt = ktb + u;                   // stage = kt&3 = u (static)
            if (kt + 1 < KT) ldgB(kt + 1);            // LDG early; hidden by mma

            mma_tile(u, u & 1);

            if (kt + 1 < KT) {
                stsB((u + 1) & 1);                    // buffer free since sync(kt-1)
                if (kt + 3 < KT) cpA(kt + 3, (u + 3) & 3);  // 3-deep A prefetch
                else             cp_commit();         // keep group count consistent
                cp_wait2();                           // A(kt+1) arrived (2 kt slack)
                __syncthreads();                      // one sync per k-tile
            }
        }
    }

    // ------------------------------ epilogue ---------------------------------
    float* Out = (MODE == 0) ? g_h : g_y2;
    const float* bp = bias + (size_t)e * NTOT;
#pragma unroll
    for (int mi = 0; mi < 4; ++mi) {
#pragma unroll
        for (int rr = 0; rr < 2; ++rr) {
            int lrow = row0 + wm * 64 + mi * 16 + gq + rr * 8;
            if (lrow < cnt) {
                float* op = Out + (size_t)(off + lrow) * NTOT;
#pragma unroll
                for (int ni = 0; ni < 4; ++ni) {
                    int c = n0 + wn * 32 + ni * 8 + tq * 2;
                    float v0 = acc[mi][ni][rr * 2 + 0] + bp[c];
                    float v1 = acc[mi][ni][rr * 2 + 1] + bp[c + 1];
                    if (MODE == 0) {   // exact GELU (erf), then rna-round for GEMM2's A
                        v0 = 0.5f * v0 * (1.f + erff(v0 * 0.70710678118654752f));
                        v1 = 0.5f * v1 * (1.f + erff(v1 * 0.70710678118654752f));
                        v0 = __uint_as_float(f2tf32(v0));
                        v1 = __uint_as_float(f2tf32(v1));
                    }
                    *reinterpret_cast<float2*>(op + c) = make_float2(v0, v1);
                }
            }
        }
    }
}

// ------------------------------- combine --------------------------------------
__global__ void k_combine(float* __restrict__ out) {
    int i = blockIdx.x * 256 + threadIdx.x;   // over T * (DM/4)
    if (i >= kT * (kDM / 4)) return;
    int t  = i >> 7;
    int d4 = i & 127;
    int a0 = t * 2, a1 = t * 2 + 1;
    float w0 = g_wa[a0], w1 = g_wa[a1];
    const float4 v0 = reinterpret_cast<const float4*>(g_y2 + (size_t)g_slot[a0] * kDM)[d4];
    const float4 v1 = reinterpret_cast<const float4*>(g_y2 + (size_t)g_slot[a1] * kDM)[d4];
    float4 r;
    r.x = w0 * v0.x + w1 * v1.x;
    r.y = w0 * v0.y + w1 * v1.y;
    r.z = w0 * v0.z + w1 * v1.z;
    r.w = w0 * v0.w + w1 * v1.w;
    reinterpret_cast<float4*>(out)[i] = r;
}

// ------------------------------- launch ----------------------------------------
extern "C" void kernel_launch(void* const* d_in, const int* in_sizes, int n_in,
                              void* d_out, int out_size) {
    const float* hidden = (const float*)d_in[0];
    const int*   cat    = (const int*)  d_in[1];
    const int*   sub    = (const int*)  d_in[2];
    const float* wts    = (const float*)d_in[3];
    const float* W1     = (const float*)d_in[4];
    const float* b1     = (const float*)d_in[5];
    const float* W2     = (const float*)d_in[6];
    const float* b2     = (const float*)d_in[7];
    float*       out    = (float*)d_out;

    (void)in_sizes; (void)n_in; (void)out_size;

    cudaFuncSetAttribute(k_gemm<kDM, kDF, 0>,
                         cudaFuncAttributeMaxDynamicSharedMemorySize, SMEM_BYTES);
    cudaFuncSetAttribute(k_gemm<kDF, kDM, 1>,
                         cudaFuncAttributeMaxDynamicSharedMemorySize, SMEM_BYTES);

    // Launch #1: fused routing (single block)
    k_route<<<1, 1024>>>(cat, sub, wts);
    // Launch #2: pre-round hidden for cp.async A path
    k_roundx<<<(kT * kDM / 4) / 256, 256>>>(hidden);

    // Launch #3: GEMM1 rows x 512 @ 512 x 2048 (+GELU) -> g_h
    dim3 g1(kDF / BN, (kCAP + BM - 1) / BM, kE);   // (16, 8, 64)
    k_gemm<kDM, kDF, 0><<<g1, NTHR, SMEM_BYTES>>>(W1, b1);

    // Launch #4 (ncu-captured): GEMM2 rows x 2048 @ 2048 x 512 -> g_y2
    dim3 g2(kDM / BN, (kCAP + BM - 1) / BM, kE);   // (4, 8, 64)
    k_gemm<kDF, kDM, 1><<<g2, NTHR, SMEM_BYTES>>>(W2, b2);

    // Launch #5: combine
    int ncomb = kT * (kDM / 4);
    k_combine<<<(ncomb + 255) / 256, 256>>>(out);
}